// round 1
// baseline (speedup 1.0000x reference)
#include <cuda_runtime.h>
#include <cuda_bf16.h>
#include <math.h>

// Problem constants
#define B_  2
#define T_  1024
#define E_  768
#define H_  12
#define L_  6
#define V_  32000
#define DH_ 64
#define DF_ 3072
#define M_  (B_*T_)   // 2048 rows

// -------------------- device scratch (no allocation allowed) --------------------
__device__ float g_x [M_*E_];
__device__ float g_h [M_*E_];
__device__ float g_q [M_*E_];
__device__ float g_k [M_*E_];
__device__ float g_v [M_*E_];
__device__ float g_o [M_*E_];
__device__ float g_ff[M_*DF_];
__device__ float g_s [(long long)B_*H_*T_*T_];   // 100.7 MB attention scores

// -------------------- embedding --------------------
__global__ __launch_bounds__(256)
void embed_kernel(const int* __restrict__ idx, const float* __restrict__ tok,
                  const float* __restrict__ pos, float* __restrict__ x)
{
    long long i = (long long)blockIdx.x * blockDim.x + threadIdx.x;
    long long total = (long long)M_ * E_;
    if (i >= total) return;
    int e  = (int)(i % E_);
    long long bt = i / E_;
    int t  = (int)(bt % T_);
    x[i] = tok[(long long)idx[bt] * E_ + e] + pos[(long long)t * E_ + e];
}

// -------------------- layernorm (one block per row) --------------------
__global__ __launch_bounds__(256)
void layernorm_kernel(const float* __restrict__ x, const float* __restrict__ g,
                      const float* __restrict__ b, float* __restrict__ out)
{
    int row = blockIdx.x;
    const float* xr = x + (long long)row * E_;
    float* orow = out + (long long)row * E_;
    int tid = threadIdx.x;

    float s = 0.f, s2 = 0.f;
    for (int e = tid; e < E_; e += 256) { float v = xr[e]; s += v; s2 += v * v; }
    #pragma unroll
    for (int off = 16; off; off >>= 1) {
        s  += __shfl_xor_sync(0xffffffffu, s,  off);
        s2 += __shfl_xor_sync(0xffffffffu, s2, off);
    }
    __shared__ float rs[8], rs2[8];
    if ((tid & 31) == 0) { rs[tid >> 5] = s; rs2[tid >> 5] = s2; }
    __syncthreads();
    float S = 0.f, S2 = 0.f;
    #pragma unroll
    for (int i = 0; i < 8; i++) { S += rs[i]; S2 += rs2[i]; }
    float mean = S * (1.f / E_);
    float var  = S2 * (1.f / E_) - mean * mean;
    float rstd = rsqrtf(var + 1e-5f);
    for (int e = tid; e < E_; e += 256)
        orow[e] = (xr[e] - mean) * rstd * g[e] + b[e];
}

// -------------------- masked softmax over score rows --------------------
__global__ __launch_bounds__(256)
void softmax_kernel(float* __restrict__ S, float scale)
{
    long long row = blockIdx.x;           // over B*H*T
    int t = (int)(row % T_);
    float* p = S + row * (long long)T_;
    int tid = threadIdx.x;

    float v[4];
    float mx = -1e30f;
    #pragma unroll
    for (int i = 0; i < 4; i++) {
        int s = tid + i * 256;
        float val = (s <= t) ? p[s] * scale : -1e30f;
        v[i] = val; mx = fmaxf(mx, val);
    }
    __shared__ float red[8];
    #pragma unroll
    for (int off = 16; off; off >>= 1) mx = fmaxf(mx, __shfl_xor_sync(0xffffffffu, mx, off));
    if ((tid & 31) == 0) red[tid >> 5] = mx;
    __syncthreads();
    float bm = red[0];
    #pragma unroll
    for (int i = 1; i < 8; i++) bm = fmaxf(bm, red[i]);

    float sum = 0.f;
    #pragma unroll
    for (int i = 0; i < 4; i++) {
        int s = tid + i * 256;
        float e = (s <= t) ? expf(v[i] - bm) : 0.f;
        v[i] = e; sum += e;
    }
    #pragma unroll
    for (int off = 16; off; off >>= 1) sum += __shfl_xor_sync(0xffffffffu, sum, off);
    __syncthreads();
    if ((tid & 31) == 0) red[tid >> 5] = sum;
    __syncthreads();
    float bs = 0.f;
    #pragma unroll
    for (int i = 0; i < 8; i++) bs += red[i];
    float inv = 1.f / bs;
    #pragma unroll
    for (int i = 0; i < 4; i++) {
        int s = tid + i * 256;
        p[s] = v[i] * inv;
    }
}

// -------------------- generic GEMM: C = A[M,K] * B[N,K]^T (+bias)(ReLU)(+resid) ----
// Tiles: 128x64x16, 256 threads, 8x4 per thread. All dims must divide tiles.
// Two-level batch: z -> (zb = z/Hdiv, zh = z%Hdiv), pointer offsets per level.
__global__ __launch_bounds__(256)
void gemm_nt_kernel(const float* __restrict__ A, int lda, long long oA1, long long oA2,
                    const float* __restrict__ Bm, int ldb, long long oB1, long long oB2,
                    float* __restrict__ C, int ldc, long long oC1, long long oC2,
                    const float* __restrict__ bias,
                    const float* __restrict__ resid,
                    int K, int Hdiv, int relu)
{
    int z  = blockIdx.z;
    int zb = z / Hdiv, zh = z % Hdiv;
    A  += zb * oA1 + zh * oA2;
    Bm += zb * oB1 + zh * oB2;
    C  += zb * oC1 + zh * oC2;
    if (resid) resid += zb * oC1 + zh * oC2;

    __shared__ float As[16][129];
    __shared__ float Bs[16][65];

    int tid = threadIdx.x;
    int tx = tid & 15, ty = tid >> 4;
    int m0 = blockIdx.y * 128;
    int n0 = blockIdx.x * 64;

    float acc[8][4] = {};

    for (int k0 = 0; k0 < K; k0 += 16) {
        #pragma unroll
        for (int i = 0; i < 8; i++) {
            int id = tid + i * 256;
            int k = id & 15, m = id >> 4;
            As[k][m] = A[(long long)(m0 + m) * lda + k0 + k];
        }
        #pragma unroll
        for (int i = 0; i < 4; i++) {
            int id = tid + i * 256;
            int k = id & 15, n = id >> 4;
            Bs[k][n] = Bm[(long long)(n0 + n) * ldb + k0 + k];
        }
        __syncthreads();
        #pragma unroll
        for (int k = 0; k < 16; k++) {
            float a[8], b[4];
            #pragma unroll
            for (int i = 0; i < 8; i++) a[i] = As[k][ty * 8 + i];
            #pragma unroll
            for (int j = 0; j < 4; j++) b[j] = Bs[k][tx * 4 + j];
            #pragma unroll
            for (int i = 0; i < 8; i++)
                #pragma unroll
                for (int j = 0; j < 4; j++)
                    acc[i][j] += a[i] * b[j];
        }
        __syncthreads();
    }

    #pragma unroll
    for (int i = 0; i < 8; i++) {
        int m = m0 + ty * 8 + i;
        #pragma unroll
        for (int j = 0; j < 4; j++) {
            int n = n0 + tx * 4 + j;
            float v = acc[i][j];
            if (bias)  v += bias[n];
            if (relu)  v = fmaxf(v, 0.f);
            if (resid) v += resid[(long long)m * ldc + n];
            C[(long long)m * ldc + n] = v;
        }
    }
}

// -------------------- GEMM NN: C = A[M,K] * B[K,N] (for P @ V) --------------------
// Tiles 64x64x16, 256 threads, 4x4 per thread.
__global__ __launch_bounds__(256)
void gemm_nn_kernel(const float* __restrict__ A, int lda, long long oA1, long long oA2,
                    const float* __restrict__ Bm, int ldb, long long oB1, long long oB2,
                    float* __restrict__ C, int ldc, long long oC1, long long oC2,
                    int K, int Hdiv)
{
    int z  = blockIdx.z;
    int zb = z / Hdiv, zh = z % Hdiv;
    A  += zb * oA1 + zh * oA2;
    Bm += zb * oB1 + zh * oB2;
    C  += zb * oC1 + zh * oC2;

    __shared__ float As[16][65];
    __shared__ float Bs[16][65];

    int tid = threadIdx.x;
    int tx = tid & 15, ty = tid >> 4;
    int m0 = blockIdx.y * 64;
    int n0 = blockIdx.x * 64;

    float acc[4][4] = {};

    for (int k0 = 0; k0 < K; k0 += 16) {
        #pragma unroll
        for (int i = 0; i < 4; i++) {
            int id = tid + i * 256;
            int k = id & 15, m = id >> 4;
            As[k][m] = A[(long long)(m0 + m) * lda + k0 + k];
        }
        #pragma unroll
        for (int i = 0; i < 4; i++) {
            int id = tid + i * 256;
            int n = id & 63, k = id >> 6;
            Bs[k][n] = Bm[(long long)(k0 + k) * ldb + n0 + n];
        }
        __syncthreads();
        #pragma unroll
        for (int k = 0; k < 16; k++) {
            float a[4], b[4];
            #pragma unroll
            for (int i = 0; i < 4; i++) a[i] = As[k][ty * 4 + i];
            #pragma unroll
            for (int j = 0; j < 4; j++) b[j] = Bs[k][tx * 4 + j];
            #pragma unroll
            for (int i = 0; i < 4; i++)
                #pragma unroll
                for (int j = 0; j < 4; j++)
                    acc[i][j] += a[i] * b[j];
        }
        __syncthreads();
    }

    #pragma unroll
    for (int i = 0; i < 4; i++) {
        int m = m0 + ty * 4 + i;
        #pragma unroll
        for (int j = 0; j < 4; j++) {
            int n = n0 + tx * 4 + j;
            C[(long long)m * ldc + n] = acc[i][j];
        }
    }
}

// -------------------- host orchestration --------------------
extern "C" void kernel_launch(void* const* d_in, const int* in_sizes, int n_in,
                              void* d_out, int out_size)
{
    const int*   idx  = (const int*)  d_in[0];
    const float* tok  = (const float*)d_in[1];
    const float* pos  = (const float*)d_in[2];
    const float* Wq   = (const float*)d_in[3];
    const float* Wk   = (const float*)d_in[4];
    const float* Wv   = (const float*)d_in[5];
    const float* Wo   = (const float*)d_in[6];
    const float* bo   = (const float*)d_in[7];
    const float* ln1g = (const float*)d_in[8];
    const float* ln1b = (const float*)d_in[9];
    const float* W1   = (const float*)d_in[10];
    const float* b1   = (const float*)d_in[11];
    const float* W2   = (const float*)d_in[12];
    const float* b2   = (const float*)d_in[13];
    const float* ln2g = (const float*)d_in[14];
    const float* ln2b = (const float*)d_in[15];
    const float* lnfg = (const float*)d_in[16];
    const float* lnfb = (const float*)d_in[17];
    const float* Wlm  = (const float*)d_in[18];
    const float* blm  = (const float*)d_in[19];
    float* out = (float*)d_out;

    float *x, *h, *q, *k, *v, *o, *ff, *s;
    cudaGetSymbolAddress((void**)&x,  g_x);
    cudaGetSymbolAddress((void**)&h,  g_h);
    cudaGetSymbolAddress((void**)&q,  g_q);
    cudaGetSymbolAddress((void**)&k,  g_k);
    cudaGetSymbolAddress((void**)&v,  g_v);
    cudaGetSymbolAddress((void**)&o,  g_o);
    cudaGetSymbolAddress((void**)&ff, g_ff);
    cudaGetSymbolAddress((void**)&s,  g_s);

    const float scale = 1.0f / sqrtf((float)E_);   // n_embd**-0.5 per reference

    // x = tok_emb[idx] + pos_emb
    {
        long long total = (long long)M_ * E_;
        int blocks = (int)((total + 255) / 256);
        embed_kernel<<<blocks, 256>>>(idx, tok, pos, x);
    }

    const long long EE = (long long)E_ * E_;

    for (int l = 0; l < L_; l++) {
        // h = LN1(x)
        layernorm_kernel<<<M_, 256>>>(x, ln1g + l * E_, ln1b + l * E_, h);

        // q/k/v = h @ W^T   (M=2048, N=768, K=768)
        {
            dim3 grid(E_ / 64, M_ / 128, 1);
            gemm_nt_kernel<<<grid, 256>>>(h, E_, 0, 0, Wq + l * EE, E_, 0, 0,
                                          q, E_, 0, 0, nullptr, nullptr, E_, 1, 0);
            gemm_nt_kernel<<<grid, 256>>>(h, E_, 0, 0, Wk + l * EE, E_, 0, 0,
                                          k, E_, 0, 0, nullptr, nullptr, E_, 1, 0);
            gemm_nt_kernel<<<grid, 256>>>(h, E_, 0, 0, Wv + l * EE, E_, 0, 0,
                                          v, E_, 0, 0, nullptr, nullptr, E_, 1, 0);
        }

        // S[b,h] = Q[b,h] @ K[b,h]^T   (batched over B*H=24; M=N=1024, K=64)
        {
            dim3 grid(T_ / 64, T_ / 128, B_ * H_);
            gemm_nt_kernel<<<grid, 256>>>(
                q, E_, (long long)T_ * E_, DH_,
                k, E_, (long long)T_ * E_, DH_,
                s, T_, (long long)H_ * T_ * T_, (long long)T_ * T_,
                nullptr, nullptr, DH_, H_, 0);
        }

        // masked softmax rows
        softmax_kernel<<<B_ * H_ * T_, 256>>>(s, scale);

        // O[b,h] = P[b,h] @ V[b,h]   (batched; M=1024, N=64, K=1024)
        {
            dim3 grid(1, T_ / 64, B_ * H_);
            gemm_nn_kernel<<<grid, 256>>>(
                s, T_, (long long)H_ * T_ * T_, (long long)T_ * T_,
                v, E_, (long long)T_ * E_, DH_,
                o, E_, (long long)T_ * E_, DH_,
                T_, H_);
        }

        // x = x + O @ Wo^T + bo
        {
            dim3 grid(E_ / 64, M_ / 128, 1);
            gemm_nt_kernel<<<grid, 256>>>(o, E_, 0, 0, Wo + l * EE, E_, 0, 0,
                                          x, E_, 0, 0, bo + l * E_, x, E_, 1, 0);
        }

        // h = LN2(x)
        layernorm_kernel<<<M_, 256>>>(x, ln2g + l * E_, ln2b + l * E_, h);

        // ff = relu(h @ W1^T + b1)   (N=3072, K=768)
        {
            dim3 grid(DF_ / 64, M_ / 128, 1);
            gemm_nt_kernel<<<grid, 256>>>(h, E_, 0, 0, W1 + (long long)l * DF_ * E_, E_, 0, 0,
                                          ff, DF_, 0, 0, b1 + l * DF_, nullptr, E_, 1, 1);
        }

        // x = x + ff @ W2^T + b2   (N=768, K=3072)
        {
            dim3 grid(E_ / 64, M_ / 128, 1);
            gemm_nt_kernel<<<grid, 256>>>(ff, DF_, 0, 0, W2 + (long long)l * E_ * DF_, DF_, 0, 0,
                                          x, E_, 0, 0, b2 + l * E_, x, DF_, 1, 0);
        }
    }

    // h = LNf(x); logits = h @ Wlm^T + blm   (N=32000, K=768)
    layernorm_kernel<<<M_, 256>>>(x, lnfg, lnfb, h);
    {
        dim3 grid(V_ / 64, M_ / 128, 1);
        gemm_nt_kernel<<<grid, 256>>>(h, E_, 0, 0, Wlm, E_, 0, 0,
                                      out, V_, 0, 0, blm, nullptr, E_, 1, 0);
    }
}

// round 3
// speedup vs baseline: 2.8385x; 2.8385x over previous
#include <cuda_runtime.h>
#include <cuda_bf16.h>
#include <cstdint>
#include <math.h>

#define B_  2
#define T_  1024
#define E_  768
#define H_  12
#define L_  6
#define V_  32000
#define DH_ 64
#define DF_ 3072
#define M_  (B_*T_)

typedef __nv_bfloat16 bf16;

// ========================= helpers =========================
__device__ __forceinline__ uint32_t smem_u32(const void* p) {
    uint32_t a;
    asm("{ .reg .u64 t; cvta.to.shared.u64 t, %1; cvt.u32.u64 %0, t; }" : "=r"(a) : "l"(p));
    return a;
}
#define LDSM4(r, addr) \
    asm volatile("ldmatrix.sync.aligned.m8n8.x4.shared.b16 {%0,%1,%2,%3}, [%4];" \
        : "=r"((r)[0]), "=r"((r)[1]), "=r"((r)[2]), "=r"((r)[3]) : "r"(addr))
#define MMA_BF16(d, a, b0, b1) \
    asm volatile("mma.sync.aligned.m16n8k16.row.col.f32.bf16.bf16.f32 " \
        "{%0,%1,%2,%3}, {%4,%5,%6,%7}, {%8,%9}, {%0,%1,%2,%3};" \
        : "+f"((d)[0]), "+f"((d)[1]), "+f"((d)[2]), "+f"((d)[3]) \
        : "r"((a)[0]), "r"((a)[1]), "r"((a)[2]), "r"((a)[3]), "r"(b0), "r"(b1))
#define CP_ASYNC16(dst, src) \
    asm volatile("cp.async.cg.shared.global [%0], [%1], 16;" :: "r"(dst), "l"(src))
#define CP_COMMIT() asm volatile("cp.async.commit_group;" ::: "memory")
#define CP_WAIT2()  asm volatile("cp.async.wait_group 2;" ::: "memory")

// ========================= device scratch =========================
__device__ bf16 g_wq_h[L_*E_*E_],  g_wq_l[L_*E_*E_];
__device__ bf16 g_wk_h[L_*E_*E_],  g_wk_l[L_*E_*E_];
__device__ bf16 g_wv_h[L_*E_*E_],  g_wv_l[L_*E_*E_];
__device__ bf16 g_wo_h[L_*E_*E_],  g_wo_l[L_*E_*E_];
__device__ bf16 g_w1_h[L_*DF_*E_], g_w1_l[L_*DF_*E_];
__device__ bf16 g_w2_h[L_*E_*DF_], g_w2_l[L_*E_*DF_];
__device__ bf16 g_wlm_h[V_*E_],    g_wlm_l[V_*E_];
__device__ bf16 g_h_h[M_*E_],  g_h_l[M_*E_];
__device__ bf16 g_q_h[M_*E_],  g_q_l[M_*E_];
__device__ bf16 g_k_h[M_*E_],  g_k_l[M_*E_];
__device__ bf16 g_v_h[M_*E_],  g_v_l[M_*E_];
__device__ bf16 g_vt_h[M_*E_], g_vt_l[M_*E_];
__device__ bf16 g_o_h[M_*E_],  g_o_l[M_*E_];
__device__ bf16 g_ff_h[M_*DF_], g_ff_l[M_*DF_];
__device__ bf16 g_p_h[(long long)B_*H_*T_*T_], g_p_l[(long long)B_*H_*T_*T_];
__device__ float g_x[M_*E_];
__device__ float g_s[(long long)B_*H_*T_*T_];

// ========================= small kernels =========================
__global__ __launch_bounds__(256)
void split_kernel(const float4* __restrict__ src, __nv_bfloat162* __restrict__ hi,
                  __nv_bfloat162* __restrict__ lo, int n4)
{
    int i = blockIdx.x * 256 + threadIdx.x;
    if (i >= n4) return;
    float4 v = src[i];
    bf16 h0 = __float2bfloat16(v.x), h1 = __float2bfloat16(v.y);
    bf16 h2 = __float2bfloat16(v.z), h3 = __float2bfloat16(v.w);
    __nv_bfloat162 a, b, c, d;
    a.x = h0; a.y = h1; b.x = h2; b.y = h3;
    c.x = __float2bfloat16(v.x - __bfloat162float(h0));
    c.y = __float2bfloat16(v.y - __bfloat162float(h1));
    d.x = __float2bfloat16(v.z - __bfloat162float(h2));
    d.y = __float2bfloat16(v.w - __bfloat162float(h3));
    hi[i*2] = a; hi[i*2+1] = b;
    lo[i*2] = c; lo[i*2+1] = d;
}

__global__ __launch_bounds__(256)
void embed_kernel(const int* __restrict__ idx, const float* __restrict__ tok,
                  const float* __restrict__ pos, float* __restrict__ x)
{
    long long i = (long long)blockIdx.x * 256 + threadIdx.x;
    if (i >= (long long)M_ * E_) return;
    int e = (int)(i % E_);
    long long bt = i / E_;
    int t = (int)(bt % T_);
    x[i] = tok[(long long)idx[bt] * E_ + e] + pos[(long long)t * E_ + e];
}

__global__ __launch_bounds__(256)
void layernorm_kernel(const float* __restrict__ x, const float* __restrict__ g,
                      const float* __restrict__ b, bf16* __restrict__ oh, bf16* __restrict__ ol)
{
    int row = blockIdx.x;
    const float* xr = x + (long long)row * E_;
    int tid = threadIdx.x;
    float s = 0.f, s2 = 0.f;
    for (int e = tid; e < E_; e += 256) { float v = xr[e]; s += v; s2 += v * v; }
    #pragma unroll
    for (int off = 16; off; off >>= 1) {
        s  += __shfl_xor_sync(0xffffffffu, s,  off);
        s2 += __shfl_xor_sync(0xffffffffu, s2, off);
    }
    __shared__ float rs[8], rs2[8];
    if ((tid & 31) == 0) { rs[tid >> 5] = s; rs2[tid >> 5] = s2; }
    __syncthreads();
    float S = 0.f, S2 = 0.f;
    #pragma unroll
    for (int i = 0; i < 8; i++) { S += rs[i]; S2 += rs2[i]; }
    float mean = S * (1.f / E_);
    float rstd = rsqrtf(S2 * (1.f / E_) - mean * mean + 1e-5f);
    for (int e = tid; e < E_; e += 256) {
        float y = (xr[e] - mean) * rstd * g[e] + b[e];
        bf16 h = __float2bfloat16(y);
        oh[(long long)row * E_ + e] = h;
        ol[(long long)row * E_ + e] = __float2bfloat16(y - __bfloat162float(h));
    }
}

__global__ __launch_bounds__(256)
void softmax_kernel(const float* __restrict__ S, bf16* __restrict__ ph,
                    bf16* __restrict__ pl, float scale)
{
    long long row = blockIdx.x;
    int t = (int)(row % T_);
    const float* p = S + row * (long long)T_;
    int tid = threadIdx.x;
    float v[4];
    float mx = -1e30f;
    #pragma unroll
    for (int i = 0; i < 4; i++) {
        int s = tid + i * 256;
        float val = (s <= t) ? p[s] * scale : -1e30f;
        v[i] = val; mx = fmaxf(mx, val);
    }
    __shared__ float red[8];
    #pragma unroll
    for (int off = 16; off; off >>= 1) mx = fmaxf(mx, __shfl_xor_sync(0xffffffffu, mx, off));
    if ((tid & 31) == 0) red[tid >> 5] = mx;
    __syncthreads();
    float bm = red[0];
    #pragma unroll
    for (int i = 1; i < 8; i++) bm = fmaxf(bm, red[i]);
    float sum = 0.f;
    #pragma unroll
    for (int i = 0; i < 4; i++) {
        int s = tid + i * 256;
        float e = (s <= t) ? expf(v[i] - bm) : 0.f;
        v[i] = e; sum += e;
    }
    #pragma unroll
    for (int off = 16; off; off >>= 1) sum += __shfl_xor_sync(0xffffffffu, sum, off);
    __syncthreads();
    if ((tid & 31) == 0) red[tid >> 5] = sum;
    __syncthreads();
    float bs = 0.f;
    #pragma unroll
    for (int i = 0; i < 8; i++) bs += red[i];
    float inv = 1.f / bs;
    bf16* oh = ph + row * (long long)T_;
    bf16* ol = pl + row * (long long)T_;
    #pragma unroll
    for (int i = 0; i < 4; i++) {
        int s = tid + i * 256;
        float y = v[i] * inv;
        bf16 h = __float2bfloat16(y);
        oh[s] = h;
        ol[s] = __float2bfloat16(y - __bfloat162float(h));
    }
}

// transpose v planes [B*T, E](head slice) -> vT planes [B,H,Dh,T]
__global__ __launch_bounds__(256)
void transpose_vT(const bf16* __restrict__ vh, const bf16* __restrict__ vl,
                  bf16* __restrict__ th, bf16* __restrict__ tl)
{
    int bh = blockIdx.y;
    int b = bh / H_, h = bh % H_;
    int t0 = blockIdx.x * 64;
    int tid = threadIdx.x;
    __shared__ bf16 tile[64][65];
    for (int pass = 0; pass < 2; pass++) {
        const bf16* src = pass ? vl : vh;
        bf16* dst = pass ? tl : th;
        #pragma unroll
        for (int i = 0; i < 16; i++) {
            int id = tid + i * 256;
            int r = id >> 6, c = id & 63;
            tile[r][c] = src[(long long)(b * T_ + t0 + r) * E_ + h * DH_ + c];
        }
        __syncthreads();
        #pragma unroll
        for (int i = 0; i < 16; i++) {
            int id = tid + i * 256;
            int d = id >> 6, tc = id & 63;
            dst[(long long)(bh * DH_ + d) * T_ + t0 + tc] = tile[tc][d];
        }
        __syncthreads();
    }
}

// ========================= mma.sync split-bf16 GEMM =========================
// C[M,N] = A[M,K] * B[N,K]^T via hi/lo planes (3 products), fp32 accum.
// CTA tile 128 x NT, K chunk 32, 4-stage cp.async pipeline.
// CMODE: 0 = none, 1 = causal skip (scores), 2 = causal K-limit (PV).
template<int NT>
__device__ __forceinline__ void issue_stage(
    uint32_t sb, int stage, int c,
    const bf16* Ahi, const bf16* Alo, int lda, int m0,
    const bf16* Bhi, const bf16* Blo, int ldb, int n0, int tid)
{
    const int SSTRIDE = (256 + 2 * NT) * 80;
    uint32_t base = sb + stage * SSTRIDE;
    int k0 = c * 32;
    #pragma unroll
    for (int i = 0; i < 4; i++) {
        int id = tid + i * 256;
        int plane = id >> 9, rid = id & 511;
        int row = rid >> 2, kq = rid & 3;
        const bf16* src = (plane ? Alo : Ahi) + (long long)(m0 + row) * lda + k0 + kq * 8;
        uint32_t dst = base + plane * 10240 + row * 80 + kq * 16;
        CP_ASYNC16(dst, src);
    }
    #pragma unroll
    for (int i = 0; i < NT / 32; i++) {
        int id = tid + i * 256;
        int plane = id / (NT * 4), rid = id % (NT * 4);
        int row = rid >> 2, kq = rid & 3;
        const bf16* src = (plane ? Blo : Bhi) + (long long)(n0 + row) * ldb + k0 + kq * 8;
        uint32_t dst = base + 20480 + plane * (NT * 80) + row * 80 + kq * 16;
        CP_ASYNC16(dst, src);
    }
}

template<int NT, int CMODE>
__global__ __launch_bounds__(256, 1)
void gemm_mma(const bf16* __restrict__ Ahi, const bf16* __restrict__ Alo,
              int lda, long long oA1, long long oA2,
              const bf16* __restrict__ Bhi, const bf16* __restrict__ Blo,
              int ldb, long long oB1, long long oB2,
              float* outF, bf16* outHi, bf16* outLo,
              int ldc, long long oC1, long long oC2,
              const float* __restrict__ bias, const float* __restrict__ resid,
              int relu, int K, int Hdiv)
{
    constexpr int S = 4;
    constexpr int SSTRIDE = (256 + 2 * NT) * 80;
    constexpr int NFR = NT / 32;   // n8 frags per warp
    constexpr int NBL = NT / 64;   // B ldmatrix.x4 per plane per k16

    extern __shared__ char smem[];
    uint32_t sb = smem_u32(smem);

    int tid = threadIdx.x, wid = tid >> 5, lane = tid & 31;
    int m0 = blockIdx.y * 128, n0 = blockIdx.x * NT;
    if (CMODE == 1 && n0 >= m0 + 128) return;

    int z = blockIdx.z, zb = z / Hdiv, zh = z % Hdiv;
    Ahi += zb * oA1 + zh * oA2;  Alo += zb * oA1 + zh * oA2;
    Bhi += zb * oB1 + zh * oB2;  Blo += zb * oB1 + zh * oB2;
    long long cOff = zb * oC1 + zh * oC2;

    int nc = K / 32;
    if (CMODE == 2) { int lim = (m0 + 128) / 32; nc = nc < lim ? nc : lim; }

    // prologue: fill S-1 stages (empty commits keep group accounting aligned)
    #pragma unroll
    for (int s = 0; s < S - 1; s++) {
        if (s < nc) issue_stage<NT>(sb, s, s, Ahi, Alo, lda, m0, Bhi, Blo, ldb, n0, tid);
        CP_COMMIT();
    }

    int wr = wid >> 2, wc = wid & 3;
    int wm = wr * 64, wn = wc * (NT / 4);

    float acc[4][NFR][4];
    #pragma unroll
    for (int a = 0; a < 4; a++)
        #pragma unroll
        for (int b = 0; b < NFR; b++)
            #pragma unroll
            for (int cc = 0; cc < 4; cc++) acc[a][b][cc] = 0.f;

    for (int c = 0; c < nc; c++) {
        CP_WAIT2();
        __syncthreads();
        uint32_t base = sb + (c & 3) * SSTRIDE;
        #pragma unroll
        for (int ks = 0; ks < 2; ks++) {
            int colb = (ks * 16 + (lane >> 4) * 8) * 2;
            int rq = lane & 15;
            uint32_t ahf[4][4], alf[4][4];
            #pragma unroll
            for (int mi = 0; mi < 4; mi++) {
                uint32_t addr = base + (wm + mi * 16 + rq) * 80 + colb;
                LDSM4(ahf[mi], addr);
                LDSM4(alf[mi], addr + 10240);
            }
            uint32_t bhf[NBL][4], blf[NBL][4];
            #pragma unroll
            for (int bj = 0; bj < NBL; bj++) {
                uint32_t addr = base + 20480 + (wn + bj * 16 + rq) * 80 + colb;
                LDSM4(bhf[bj], addr);
                LDSM4(blf[bj], addr + NT * 80);
            }
            #pragma unroll
            for (int mi = 0; mi < 4; mi++)
                #pragma unroll
                for (int bj = 0; bj < NBL; bj++)
                    #pragma unroll
                    for (int hf = 0; hf < 2; hf++) {
                        int nf = bj * 2 + hf;
                        MMA_BF16(acc[mi][nf], ahf[mi], bhf[bj][hf], bhf[bj][hf + 2]);
                        MMA_BF16(acc[mi][nf], ahf[mi], blf[bj][hf], blf[bj][hf + 2]);
                        MMA_BF16(acc[mi][nf], alf[mi], bhf[bj][hf], bhf[bj][hf + 2]);
                    }
        }
        if (c + S - 1 < nc)
            issue_stage<NT>(sb, (c + 3) & 3, c + 3, Ahi, Alo, lda, m0, Bhi, Blo, ldb, n0, tid);
        CP_COMMIT();
    }

    // epilogue
    #pragma unroll
    for (int mi = 0; mi < 4; mi++) {
        #pragma unroll
        for (int nf = 0; nf < NFR; nf++) {
            int col = n0 + wn + nf * 8 + (lane & 3) * 2;
            #pragma unroll
            for (int hf = 0; hf < 2; hf++) {
                int row = m0 + wm + mi * 16 + (lane >> 2) + hf * 8;
                float v0 = acc[mi][nf][hf * 2], v1 = acc[mi][nf][hf * 2 + 1];
                if (bias) { v0 += __ldg(bias + col); v1 += __ldg(bias + col + 1); }
                if (relu) { v0 = fmaxf(v0, 0.f); v1 = fmaxf(v1, 0.f); }
                long long off = cOff + (long long)row * ldc + col;
                if (resid) { float2 r = *(const float2*)(resid + off); v0 += r.x; v1 += r.y; }
                if (outF) { float2 ov; ov.x = v0; ov.y = v1; *(float2*)(outF + off) = ov; }
                if (outHi) {
                    bf16 h0 = __float2bfloat16(v0), h1 = __float2bfloat16(v1);
                    __nv_bfloat162 hh2, ll2;
                    hh2.x = h0; hh2.y = h1;
                    ll2.x = __float2bfloat16(v0 - __bfloat162float(h0));
                    ll2.y = __float2bfloat16(v1 - __bfloat162float(h1));
                    *(__nv_bfloat162*)(outHi + off) = hh2;
                    *(__nv_bfloat162*)(outLo + off) = ll2;
                }
            }
        }
    }
}

// ========================= host =========================
static inline void split_launch(const float* src, bf16* hi, bf16* lo, long long n)
{
    int n4 = (int)(n / 4);
    split_kernel<<<(n4 + 255) / 256, 256>>>((const float4*)src, (__nv_bfloat162*)hi, (__nv_bfloat162*)lo, n4);
}

extern "C" void kernel_launch(void* const* d_in, const int* in_sizes, int n_in,
                              void* d_out, int out_size)
{
    const int*   idx  = (const int*)  d_in[0];
    const float* tok  = (const float*)d_in[1];
    const float* pos  = (const float*)d_in[2];
    const float* Wq   = (const float*)d_in[3];
    const float* Wk   = (const float*)d_in[4];
    const float* Wv   = (const float*)d_in[5];
    const float* Wo   = (const float*)d_in[6];
    const float* bo   = (const float*)d_in[7];
    const float* ln1g = (const float*)d_in[8];
    const float* ln1b = (const float*)d_in[9];
    const float* W1   = (const float*)d_in[10];
    const float* b1   = (const float*)d_in[11];
    const float* W2   = (const float*)d_in[12];
    const float* b2   = (const float*)d_in[13];
    const float* ln2g = (const float*)d_in[14];
    const float* ln2b = (const float*)d_in[15];
    const float* lnfg = (const float*)d_in[16];
    const float* lnfb = (const float*)d_in[17];
    const float* Wlm  = (const float*)d_in[18];
    const float* blm  = (const float*)d_in[19];
    float* out = (float*)d_out;

    bf16 *wqh,*wql,*wkh,*wkl,*wvh,*wvl,*woh,*wol,*w1h,*w1l,*w2h,*w2l,*wlmh,*wlml;
    bf16 *hh,*hl,*qh,*ql,*kh,*kl,*vh,*vl,*vth,*vtl,*oh,*ol,*ffh,*ffl,*pph,*ppl;
    float *x,*s;
    cudaGetSymbolAddress((void**)&wqh, g_wq_h);  cudaGetSymbolAddress((void**)&wql, g_wq_l);
    cudaGetSymbolAddress((void**)&wkh, g_wk_h);  cudaGetSymbolAddress((void**)&wkl, g_wk_l);
    cudaGetSymbolAddress((void**)&wvh, g_wv_h);  cudaGetSymbolAddress((void**)&wvl, g_wv_l);
    cudaGetSymbolAddress((void**)&woh, g_wo_h);  cudaGetSymbolAddress((void**)&wol, g_wo_l);
    cudaGetSymbolAddress((void**)&w1h, g_w1_h);  cudaGetSymbolAddress((void**)&w1l, g_w1_l);
    cudaGetSymbolAddress((void**)&w2h, g_w2_h);  cudaGetSymbolAddress((void**)&w2l, g_w2_l);
    cudaGetSymbolAddress((void**)&wlmh, g_wlm_h); cudaGetSymbolAddress((void**)&wlml, g_wlm_l);
    cudaGetSymbolAddress((void**)&hh, g_h_h);    cudaGetSymbolAddress((void**)&hl, g_h_l);
    cudaGetSymbolAddress((void**)&qh, g_q_h);    cudaGetSymbolAddress((void**)&ql, g_q_l);
    cudaGetSymbolAddress((void**)&kh, g_k_h);    cudaGetSymbolAddress((void**)&kl, g_k_l);
    cudaGetSymbolAddress((void**)&vh, g_v_h);    cudaGetSymbolAddress((void**)&vl, g_v_l);
    cudaGetSymbolAddress((void**)&vth, g_vt_h);  cudaGetSymbolAddress((void**)&vtl, g_vt_l);
    cudaGetSymbolAddress((void**)&oh, g_o_h);    cudaGetSymbolAddress((void**)&ol, g_o_l);
    cudaGetSymbolAddress((void**)&ffh, g_ff_h);  cudaGetSymbolAddress((void**)&ffl, g_ff_l);
    cudaGetSymbolAddress((void**)&pph, g_p_h);   cudaGetSymbolAddress((void**)&ppl, g_p_l);
    cudaGetSymbolAddress((void**)&x, g_x);       cudaGetSymbolAddress((void**)&s, g_s);

    const int SM128 = 4 * (256 + 256) * 80;  // 163840
    const int SM64  = 4 * (256 + 128) * 80;  // 122880
    cudaFuncSetAttribute(gemm_mma<128,0>, cudaFuncAttributeMaxDynamicSharedMemorySize, SM128);
    cudaFuncSetAttribute(gemm_mma<128,1>, cudaFuncAttributeMaxDynamicSharedMemorySize, SM128);
    cudaFuncSetAttribute(gemm_mma<64,2>,  cudaFuncAttributeMaxDynamicSharedMemorySize, SM64);

    split_launch(Wq, wqh, wql, (long long)L_*E_*E_);
    split_launch(Wk, wkh, wkl, (long long)L_*E_*E_);
    split_launch(Wv, wvh, wvl, (long long)L_*E_*E_);
    split_launch(Wo, woh, wol, (long long)L_*E_*E_);
    split_launch(W1, w1h, w1l, (long long)L_*DF_*E_);
    split_launch(W2, w2h, w2l, (long long)L_*E_*DF_);
    split_launch(Wlm, wlmh, wlml, (long long)V_*E_);

    const float scale = 1.0f / sqrtf((float)E_);

    embed_kernel<<<(int)(((long long)M_*E_ + 255)/256), 256>>>(idx, tok, pos, x);

    const long long EE = (long long)E_ * E_;
    for (int l = 0; l < L_; l++) {
        layernorm_kernel<<<M_, 256>>>(x, ln1g + l*E_, ln1b + l*E_, hh, hl);

        dim3 g1(E_/128, M_/128, 1);
        gemm_mma<128,0><<<g1, 256, SM128>>>(hh, hl, E_, 0, 0, wqh + l*EE, wql + l*EE, E_, 0, 0,
            nullptr, qh, ql, E_, 0, 0, nullptr, nullptr, 0, E_, 1);
        gemm_mma<128,0><<<g1, 256, SM128>>>(hh, hl, E_, 0, 0, wkh + l*EE, wkl + l*EE, E_, 0, 0,
            nullptr, kh, kl, E_, 0, 0, nullptr, nullptr, 0, E_, 1);
        gemm_mma<128,0><<<g1, 256, SM128>>>(hh, hl, E_, 0, 0, wvh + l*EE, wvl + l*EE, E_, 0, 0,
            nullptr, vh, vl, E_, 0, 0, nullptr, nullptr, 0, E_, 1);

        // S = Q @ K^T (fp32), causal tile skip
        {
            dim3 g(T_/128, T_/128, B_*H_);
            gemm_mma<128,1><<<g, 256, SM128>>>(
                qh, ql, E_, (long long)T_*E_, DH_,
                kh, kl, E_, (long long)T_*E_, DH_,
                s, nullptr, nullptr, T_, (long long)H_*T_*T_, (long long)T_*T_,
                nullptr, nullptr, 0, DH_, H_);
        }
        softmax_kernel<<<B_*H_*T_, 256>>>(s, pph, ppl, scale);

        {
            dim3 g(T_/64, B_*H_);
            transpose_vT<<<g, 256>>>(vh, vl, vth, vtl);
        }

        // O = P @ V via vT, causal K-limit
        {
            dim3 g(1, T_/128, B_*H_);
            gemm_mma<64,2><<<g, 256, SM64>>>(
                pph, ppl, T_, (long long)H_*T_*T_, (long long)T_*T_,
                vth, vtl, T_, (long long)H_*DH_*T_, (long long)DH_*T_,
                nullptr, oh, ol, E_, (long long)T_*E_, DH_,
                nullptr, nullptr, 0, T_, H_);
        }

        // x = x + O @ Wo^T + bo
        gemm_mma<128,0><<<g1, 256, SM128>>>(oh, ol, E_, 0, 0, woh + l*EE, wol + l*EE, E_, 0, 0,
            x, nullptr, nullptr, E_, 0, 0, bo + l*E_, x, 0, E_, 1);

        layernorm_kernel<<<M_, 256>>>(x, ln2g + l*E_, ln2b + l*E_, hh, hl);

        {
            dim3 g(DF_/128, M_/128, 1);
            gemm_mma<128,0><<<g, 256, SM128>>>(hh, hl, E_, 0, 0,
                w1h + (long long)l*DF_*E_, w1l + (long long)l*DF_*E_, E_, 0, 0,
                nullptr, ffh, ffl, DF_, 0, 0, b1 + l*DF_, nullptr, 1, E_, 1);
        }
        gemm_mma<128,0><<<g1, 256, SM128>>>(ffh, ffl, DF_, 0, 0,
            w2h + (long long)l*E_*DF_, w2l + (long long)l*E_*DF_, DF_, 0, 0,
            x, nullptr, nullptr, E_, 0, 0, b2 + l*E_, x, 0, DF_, 1);
    }

    layernorm_kernel<<<M_, 256>>>(x, lnfg, lnfb, hh, hl);
    {
        dim3 g(V_/128, M_/128, 1);
        gemm_mma<128,0><<<g, 256, SM128>>>(hh, hl, E_, 0, 0, wlmh, wlml, E_, 0, 0,
            out, nullptr, nullptr, V_, 0, 0, blm, nullptr, 0, E_, 1);
    }
}

// round 4
// speedup vs baseline: 3.2841x; 1.1570x over previous
#include <cuda_runtime.h>
#include <cuda_bf16.h>
#include <cstdint>
#include <math.h>

#define B_  2
#define T_  1024
#define E_  768
#define H_  12
#define L_  6
#define V_  32000
#define DH_ 64
#define DF_ 3072
#define M_  (B_*T_)

typedef __nv_bfloat16 bf16;

// ========================= helpers =========================
__device__ __forceinline__ uint32_t smem_u32(const void* p) {
    uint32_t a;
    asm("{ .reg .u64 t; cvta.to.shared.u64 t, %1; cvt.u32.u64 %0, t; }" : "=r"(a) : "l"(p));
    return a;
}
#define LDSM4(r, addr) \
    asm volatile("ldmatrix.sync.aligned.m8n8.x4.shared.b16 {%0,%1,%2,%3}, [%4];" \
        : "=r"((r)[0]), "=r"((r)[1]), "=r"((r)[2]), "=r"((r)[3]) : "r"(addr))
#define MMA_BF16(d, a, b0, b1) \
    asm volatile("mma.sync.aligned.m16n8k16.row.col.f32.bf16.bf16.f32 " \
        "{%0,%1,%2,%3}, {%4,%5,%6,%7}, {%8,%9}, {%0,%1,%2,%3};" \
        : "+f"((d)[0]), "+f"((d)[1]), "+f"((d)[2]), "+f"((d)[3]) \
        : "r"((a)[0]), "r"((a)[1]), "r"((a)[2]), "r"((a)[3]), "r"(b0), "r"(b1))
#define CP_ASYNC16(dst, src) \
    asm volatile("cp.async.cg.shared.global [%0], [%1], 16;" :: "r"(dst), "l"(src))
#define CP_COMMIT() asm volatile("cp.async.commit_group;" ::: "memory")
#define CP_WAIT2()  asm volatile("cp.async.wait_group 2;" ::: "memory")
#define CP_WAIT1()  asm volatile("cp.async.wait_group 1;" ::: "memory")
#define CP_WAIT0()  asm volatile("cp.async.wait_group 0;" ::: "memory")

__device__ __forceinline__ void split2(float x, float y, uint32_t& hi, uint32_t& lo) {
    bf16 hx = __float2bfloat16(x), hy = __float2bfloat16(y);
    __nv_bfloat162 Hp, Lp;
    Hp.x = hx; Hp.y = hy;
    Lp.x = __float2bfloat16(x - __bfloat162float(hx));
    Lp.y = __float2bfloat16(y - __bfloat162float(hy));
    hi = *(uint32_t*)&Hp; lo = *(uint32_t*)&Lp;
}

// ========================= device scratch =========================
__device__ bf16 g_wqkv_h[L_*3*E_*E_], g_wqkv_l[L_*3*E_*E_];
__device__ bf16 g_wo_h[L_*E_*E_],  g_wo_l[L_*E_*E_];
__device__ bf16 g_w1_h[L_*DF_*E_], g_w1_l[L_*DF_*E_];
__device__ bf16 g_w2_h[L_*E_*DF_], g_w2_l[L_*E_*DF_];
__device__ bf16 g_wlm_h[V_*E_],    g_wlm_l[V_*E_];
__device__ bf16 g_h_h[M_*E_],  g_h_l[M_*E_];
__device__ bf16 g_q_h[M_*E_],  g_q_l[M_*E_];
__device__ bf16 g_k_h[M_*E_],  g_k_l[M_*E_];
__device__ bf16 g_v_h[M_*E_],  g_v_l[M_*E_];
__device__ bf16 g_vt_h[M_*E_], g_vt_l[M_*E_];
__device__ bf16 g_o_h[M_*E_],  g_o_l[M_*E_];
__device__ bf16 g_ff_h[M_*DF_], g_ff_l[M_*DF_];
__device__ float g_x[M_*E_];

// ========================= small kernels =========================
__global__ __launch_bounds__(256)
void split_kernel(const float4* __restrict__ src, __nv_bfloat162* __restrict__ hi,
                  __nv_bfloat162* __restrict__ lo, int n4)
{
    int i = blockIdx.x * 256 + threadIdx.x;
    if (i >= n4) return;
    float4 v = src[i];
    bf16 h0 = __float2bfloat16(v.x), h1 = __float2bfloat16(v.y);
    bf16 h2 = __float2bfloat16(v.z), h3 = __float2bfloat16(v.w);
    __nv_bfloat162 a, b, c, d;
    a.x = h0; a.y = h1; b.x = h2; b.y = h3;
    c.x = __float2bfloat16(v.x - __bfloat162float(h0));
    c.y = __float2bfloat16(v.y - __bfloat162float(h1));
    d.x = __float2bfloat16(v.z - __bfloat162float(h2));
    d.y = __float2bfloat16(v.w - __bfloat162float(h3));
    hi[i*2] = a; hi[i*2+1] = b;
    lo[i*2] = c; lo[i*2+1] = d;
}

__global__ __launch_bounds__(256)
void embed_kernel(const int* __restrict__ idx, const float* __restrict__ tok,
                  const float* __restrict__ pos, float* __restrict__ x)
{
    long long i = (long long)blockIdx.x * 256 + threadIdx.x;
    if (i >= (long long)M_ * E_) return;
    int e = (int)(i % E_);
    long long bt = i / E_;
    int t = (int)(bt % T_);
    x[i] = tok[(long long)idx[bt] * E_ + e] + pos[(long long)t * E_ + e];
}

__global__ __launch_bounds__(256)
void layernorm_kernel(const float* __restrict__ x, const float* __restrict__ g,
                      const float* __restrict__ b, bf16* __restrict__ oh, bf16* __restrict__ ol)
{
    int row = blockIdx.x;
    const float* xr = x + (long long)row * E_;
    int tid = threadIdx.x;
    float s = 0.f, s2 = 0.f;
    for (int e = tid; e < E_; e += 256) { float v = xr[e]; s += v; s2 += v * v; }
    #pragma unroll
    for (int off = 16; off; off >>= 1) {
        s  += __shfl_xor_sync(0xffffffffu, s,  off);
        s2 += __shfl_xor_sync(0xffffffffu, s2, off);
    }
    __shared__ float rs[8], rs2[8];
    if ((tid & 31) == 0) { rs[tid >> 5] = s; rs2[tid >> 5] = s2; }
    __syncthreads();
    float S = 0.f, S2 = 0.f;
    #pragma unroll
    for (int i = 0; i < 8; i++) { S += rs[i]; S2 += rs2[i]; }
    float mean = S * (1.f / E_);
    float rstd = rsqrtf(S2 * (1.f / E_) - mean * mean + 1e-5f);
    for (int e = tid; e < E_; e += 256) {
        float y = (xr[e] - mean) * rstd * g[e] + b[e];
        bf16 h = __float2bfloat16(y);
        oh[(long long)row * E_ + e] = h;
        ol[(long long)row * E_ + e] = __float2bfloat16(y - __bfloat162float(h));
    }
}

// transpose v planes [B*T, E](head slice) -> vT planes [B,H,Dh,T]
__global__ __launch_bounds__(256)
void transpose_vT(const bf16* __restrict__ vh, const bf16* __restrict__ vl,
                  bf16* __restrict__ th, bf16* __restrict__ tl)
{
    int bh = blockIdx.y;
    int b = bh / H_, h = bh % H_;
    int t0 = blockIdx.x * 64;
    int tid = threadIdx.x;
    __shared__ bf16 tile[64][65];
    for (int pass = 0; pass < 2; pass++) {
        const bf16* src = pass ? vl : vh;
        bf16* dst = pass ? tl : th;
        #pragma unroll
        for (int i = 0; i < 16; i++) {
            int id = tid + i * 256;
            int r = id >> 6, c = id & 63;
            tile[r][c] = src[(long long)(b * T_ + t0 + r) * E_ + h * DH_ + c];
        }
        __syncthreads();
        #pragma unroll
        for (int i = 0; i < 16; i++) {
            int id = tid + i * 256;
            int d = id >> 6, tc = id & 63;
            dst[(long long)(bh * DH_ + d) * T_ + t0 + tc] = tile[tc][d];
        }
        __syncthreads();
    }
}

// ========================= mma.sync split-bf16 GEMM =========================
template<int NT>
__device__ __forceinline__ void issue_stage(
    uint32_t sb, int stage, int c,
    const bf16* Ahi, const bf16* Alo, int lda, int m0,
    const bf16* Bhi, const bf16* Blo, int ldb, int n0, int tid)
{
    const int SSTRIDE = (256 + 2 * NT) * 80;
    uint32_t base = sb + stage * SSTRIDE;
    int k0 = c * 32;
    #pragma unroll
    for (int i = 0; i < 4; i++) {
        int id = tid + i * 256;
        int plane = id >> 9, rid = id & 511;
        int row = rid >> 2, kq = rid & 3;
        const bf16* src = (plane ? Alo : Ahi) + (long long)(m0 + row) * lda + k0 + kq * 8;
        uint32_t dst = base + plane * 10240 + row * 80 + kq * 16;
        CP_ASYNC16(dst, src);
    }
    #pragma unroll
    for (int i = 0; i < NT / 32; i++) {
        int id = tid + i * 256;
        int plane = id / (NT * 4), rid = id % (NT * 4);
        int row = rid >> 2, kq = rid & 3;
        const bf16* src = (plane ? Blo : Bhi) + (long long)(n0 + row) * ldb + k0 + kq * 8;
        uint32_t dst = base + 20480 + plane * (NT * 80) + row * 80 + kq * 16;
        CP_ASYNC16(dst, src);
    }
}

template<int NT>
__global__ __launch_bounds__(256, 1)
void gemm_mma(const bf16* __restrict__ Ahi, const bf16* __restrict__ Alo,
              int lda, long long oA1, long long oA2,
              const bf16* __restrict__ Bhi, const bf16* __restrict__ Blo,
              int ldb, long long oB1, long long oB2,
              float* outF,
              bf16* o0h, bf16* o0l, bf16* o1h, bf16* o1l, bf16* o2h, bf16* o2l, int nRoute,
              int ldc, long long oC1, long long oC2,
              const float* __restrict__ bias, const float* __restrict__ resid,
              int relu, int K, int Hdiv)
{
    constexpr int S = 4;
    constexpr int SSTRIDE = (256 + 2 * NT) * 80;
    constexpr int NFR = NT / 32;
    constexpr int NBL = NT / 64;

    extern __shared__ char smem[];
    uint32_t sb = smem_u32(smem);

    int tid = threadIdx.x, wid = tid >> 5, lane = tid & 31;
    int m0 = blockIdx.y * 128, n0 = blockIdx.x * NT;

    int z = blockIdx.z, zb = z / Hdiv, zh = z % Hdiv;
    Ahi += zb * oA1 + zh * oA2;  Alo += zb * oA1 + zh * oA2;
    Bhi += zb * oB1 + zh * oB2;  Blo += zb * oB1 + zh * oB2;
    long long cOff = zb * oC1 + zh * oC2;

    int nc = K / 32;

    #pragma unroll
    for (int s = 0; s < S - 1; s++) {
        if (s < nc) issue_stage<NT>(sb, s, s, Ahi, Alo, lda, m0, Bhi, Blo, ldb, n0, tid);
        CP_COMMIT();
    }

    int wr = wid >> 2, wc = wid & 3;
    int wm = wr * 64, wn = wc * (NT / 4);

    float acc[4][NFR][4];
    #pragma unroll
    for (int a = 0; a < 4; a++)
        #pragma unroll
        for (int b = 0; b < NFR; b++)
            #pragma unroll
            for (int cc = 0; cc < 4; cc++) acc[a][b][cc] = 0.f;

    for (int c = 0; c < nc; c++) {
        CP_WAIT2();
        __syncthreads();
        uint32_t base = sb + (c & 3) * SSTRIDE;
        #pragma unroll
        for (int ks = 0; ks < 2; ks++) {
            int colb = (ks * 16 + (lane >> 4) * 8) * 2;
            int rq = lane & 15;
            uint32_t ahf[4][4], alf[4][4];
            #pragma unroll
            for (int mi = 0; mi < 4; mi++) {
                uint32_t addr = base + (wm + mi * 16 + rq) * 80 + colb;
                LDSM4(ahf[mi], addr);
                LDSM4(alf[mi], addr + 10240);
            }
            uint32_t bhf[NBL][4], blf[NBL][4];
            #pragma unroll
            for (int bj = 0; bj < NBL; bj++) {
                uint32_t addr = base + 20480 + (wn + bj * 16 + rq) * 80 + colb;
                LDSM4(bhf[bj], addr);
                LDSM4(blf[bj], addr + NT * 80);
            }
            #pragma unroll
            for (int mi = 0; mi < 4; mi++)
                #pragma unroll
                for (int bj = 0; bj < NBL; bj++)
                    #pragma unroll
                    for (int hf = 0; hf < 2; hf++) {
                        int nf = bj * 2 + hf;
                        MMA_BF16(acc[mi][nf], ahf[mi], bhf[bj][hf], bhf[bj][hf + 2]);
                        MMA_BF16(acc[mi][nf], ahf[mi], blf[bj][hf], blf[bj][hf + 2]);
                        MMA_BF16(acc[mi][nf], alf[mi], bhf[bj][hf], bhf[bj][hf + 2]);
                    }
        }
        if (c + S - 1 < nc)
            issue_stage<NT>(sb, (c + 3) & 3, c + 3, Ahi, Alo, lda, m0, Bhi, Blo, ldb, n0, tid);
        CP_COMMIT();
    }

    // epilogue (with optional n-routing for fused QKV)
    bf16 *OH = o0h, *OL = o0l;
    int coff = 0;
    if (nRoute) {
        int sel = n0 / nRoute;
        coff = sel * nRoute;
        if (sel == 1) { OH = o1h; OL = o1l; }
        else if (sel == 2) { OH = o2h; OL = o2l; }
    }
    #pragma unroll
    for (int mi = 0; mi < 4; mi++) {
        #pragma unroll
        for (int nf = 0; nf < NFR; nf++) {
            int col = n0 + wn + nf * 8 + (lane & 3) * 2;
            #pragma unroll
            for (int hf = 0; hf < 2; hf++) {
                int row = m0 + wm + mi * 16 + (lane >> 2) + hf * 8;
                float v0 = acc[mi][nf][hf * 2], v1 = acc[mi][nf][hf * 2 + 1];
                if (bias) { v0 += __ldg(bias + col); v1 += __ldg(bias + col + 1); }
                if (relu) { v0 = fmaxf(v0, 0.f); v1 = fmaxf(v1, 0.f); }
                long long off = cOff + (long long)row * ldc + (col - coff);
                if (resid) { float2 r = *(const float2*)(resid + off); v0 += r.x; v1 += r.y; }
                if (outF) { float2 ov; ov.x = v0; ov.y = v1; *(float2*)(outF + off) = ov; }
                if (OH) {
                    uint32_t hp, lp;
                    split2(v0, v1, hp, lp);
                    *(uint32_t*)(OH + off) = hp;
                    *(uint32_t*)(OL + off) = lp;
                }
            }
        }
    }
}

// ========================= fused flash attention =========================
// One CTA per (bh, 128-row q tile). 8 warps x 16 rows.
// Q tile resident; loop causal K/V tiles (double-buffered cp.async).
// Split-bf16 3-product for both S=QK^T and O=PV; online softmax in fragments.
#define FA_QS   144            // Q/K smem row stride bytes (64 bf16 + pad)
#define FA_VS   272            // V smem row stride bytes (128 bf16 + pad)
#define FA_QPL  (128*FA_QS)    // one Q/K plane (18432)
#define FA_KOFF (2*FA_QPL)
#define FA_KBUF (2*FA_QPL)
#define FA_VOFF (FA_KOFF + 2*FA_KBUF)
#define FA_VPL  (64*FA_VS)
#define FA_VBUF (2*FA_VPL)
#define FA_SMEM (FA_VOFF + 2*FA_VBUF)   // 180224

__device__ __forceinline__ void fa_issue_kv(
    uint32_t sb, int buf, int j,
    const bf16* kh, const bf16* kl, const bf16* vth, const bf16* vtl,
    int b, int h, int bh, int tid)
{
    int n0 = j * 128;
    const bf16* kbh = kh + (long long)(b * T_ + n0) * E_ + h * DH_;
    const bf16* kbl = kl + (long long)(b * T_ + n0) * E_ + h * DH_;
    uint32_t kb = sb + FA_KOFF + buf * FA_KBUF;
    #pragma unroll
    for (int i = 0; i < 8; i++) {
        int id = tid + i * 256;
        int plane = id >> 10, rid = id & 1023;
        int row = rid >> 3, qd = rid & 7;
        const bf16* src = (plane ? kbl : kbh) + (long long)row * E_ + qd * 8;
        CP_ASYNC16(kb + plane * FA_QPL + row * FA_QS + qd * 16, src);
    }
    const bf16* vbh = vth + (long long)(bh * DH_) * T_ + n0;
    const bf16* vbl = vtl + (long long)(bh * DH_) * T_ + n0;
    uint32_t vb = sb + FA_VOFF + buf * FA_VBUF;
    #pragma unroll
    for (int i = 0; i < 8; i++) {
        int id = tid + i * 256;
        int plane = id >> 10, rid = id & 1023;
        int row = rid >> 4, qd = rid & 15;
        const bf16* src = (plane ? vbl : vbh) + (long long)row * T_ + qd * 8;
        CP_ASYNC16(vb + plane * FA_VPL + row * FA_VS + qd * 16, src);
    }
}

__global__ __launch_bounds__(256, 1)
void flash_kernel(const bf16* __restrict__ qh, const bf16* __restrict__ ql,
                  const bf16* __restrict__ kh, const bf16* __restrict__ kl,
                  const bf16* __restrict__ vth, const bf16* __restrict__ vtl,
                  bf16* __restrict__ oh, bf16* __restrict__ ol, float scale)
{
    extern __shared__ char smem[];
    uint32_t sb = smem_u32(smem);
    int tid = threadIdx.x, wid = tid >> 5, lane = tid & 31;
    int bh = blockIdx.z;
    int b = bh / H_, h = bh % H_;
    int mt = (int)gridDim.y - 1 - (int)blockIdx.y;   // heavy tiles first
    int m0 = mt * 128;

    // load Q (group 0)
    {
        const bf16* qbh = qh + (long long)(b * T_ + m0) * E_ + h * DH_;
        const bf16* qbl = ql + (long long)(b * T_ + m0) * E_ + h * DH_;
        #pragma unroll
        for (int i = 0; i < 8; i++) {
            int id = tid + i * 256;
            int plane = id >> 10, rid = id & 1023;
            int row = rid >> 3, qd = rid & 7;
            const bf16* src = (plane ? qbl : qbh) + (long long)row * E_ + qd * 8;
            CP_ASYNC16(sb + plane * FA_QPL + row * FA_QS + qd * 16, src);
        }
        CP_COMMIT();
    }
    // load K0/V0 (group 1)
    fa_issue_kv(sb, 0, 0, kh, kl, vth, vtl, b, h, bh, tid);
    CP_COMMIT();

    int wr0 = wid * 16;
    int ra = lane >> 2;      // local row a; row b = ra+8
    int rq = lane & 15;

    float m_a = -1e30f, m_b = -1e30f, l_a = 0.f, l_b = 0.f;
    float accO[8][4];
    #pragma unroll
    for (int i = 0; i < 8; i++)
        #pragma unroll
        for (int c = 0; c < 4; c++) accO[i][c] = 0.f;

    for (int j = 0; j <= mt; j++) {
        __syncthreads();   // all warps done reading buffer about to be overwritten
        if (j < mt) {
            fa_issue_kv(sb, (j + 1) & 1, j + 1, kh, kl, vth, vtl, b, h, bh, tid);
            CP_COMMIT();
            CP_WAIT1();
        } else {
            CP_WAIT0();
        }
        __syncthreads();

        uint32_t kb = sb + FA_KOFF + (j & 1) * FA_KBUF;
        uint32_t vb = sb + FA_VOFF + (j & 1) * FA_VBUF;

        // ---- S = Q K^T (128-col stripe, 16 rows per warp) ----
        float accS[16][4];
        #pragma unroll
        for (int i = 0; i < 16; i++)
            #pragma unroll
            for (int c = 0; c < 4; c++) accS[i][c] = 0.f;

        #pragma unroll
        for (int ks = 0; ks < 4; ks++) {
            int colb = (ks * 16 + (lane >> 4) * 8) * 2;
            uint32_t ahf[4], alf[4];
            uint32_t qaddr = sb + (wr0 + rq) * FA_QS + colb;
            LDSM4(ahf, qaddr);
            LDSM4(alf, qaddr + FA_QPL);
            #pragma unroll
            for (int bj = 0; bj < 8; bj++) {
                uint32_t bhf[4], blf[4];
                uint32_t kaddr = kb + (bj * 16 + rq) * FA_QS + colb;
                LDSM4(bhf, kaddr);
                LDSM4(blf, kaddr + FA_QPL);
                #pragma unroll
                for (int hf = 0; hf < 2; hf++) {
                    int nf = bj * 2 + hf;
                    MMA_BF16(accS[nf], ahf, bhf[hf], bhf[hf + 2]);
                    MMA_BF16(accS[nf], ahf, blf[hf], blf[hf + 2]);
                    MMA_BF16(accS[nf], alf, bhf[hf], bhf[hf + 2]);
                }
            }
        }

        // ---- scale + causal mask + online softmax ----
        bool diag = (j == mt);
        int rla = wr0 + ra, rlb = rla + 8;
        float mxa = m_a, mxb = m_b;
        #pragma unroll
        for (int nf = 0; nf < 16; nf++) {
            #pragma unroll
            for (int c2 = 0; c2 < 2; c2++) {
                int cl = nf * 8 + (lane & 3) * 2 + c2;
                float va = accS[nf][c2] * scale;
                float vb2 = accS[nf][2 + c2] * scale;
                if (diag) {
                    if (cl > rla) va = -1e30f;
                    if (cl > rlb) vb2 = -1e30f;
                }
                accS[nf][c2] = va; accS[nf][2 + c2] = vb2;
                mxa = fmaxf(mxa, va); mxb = fmaxf(mxb, vb2);
            }
        }
        mxa = fmaxf(mxa, __shfl_xor_sync(0xffffffffu, mxa, 1));
        mxa = fmaxf(mxa, __shfl_xor_sync(0xffffffffu, mxa, 2));
        mxb = fmaxf(mxb, __shfl_xor_sync(0xffffffffu, mxb, 1));
        mxb = fmaxf(mxb, __shfl_xor_sync(0xffffffffu, mxb, 2));
        float ca = __expf(m_a - mxa), cb = __expf(m_b - mxb);
        m_a = mxa; m_b = mxb;
        #pragma unroll
        for (int i = 0; i < 8; i++) {
            accO[i][0] *= ca; accO[i][1] *= ca;
            accO[i][2] *= cb; accO[i][3] *= cb;
        }
        float suma = 0.f, sumb = 0.f;
        #pragma unroll
        for (int nf = 0; nf < 16; nf++) {
            #pragma unroll
            for (int c2 = 0; c2 < 2; c2++) {
                float pa = __expf(accS[nf][c2] - m_a);
                float pb = __expf(accS[nf][2 + c2] - m_b);
                accS[nf][c2] = pa; accS[nf][2 + c2] = pb;
                suma += pa; sumb += pb;
            }
        }
        suma += __shfl_xor_sync(0xffffffffu, suma, 1);
        suma += __shfl_xor_sync(0xffffffffu, suma, 2);
        sumb += __shfl_xor_sync(0xffffffffu, sumb, 1);
        sumb += __shfl_xor_sync(0xffffffffu, sumb, 2);
        l_a = l_a * ca + suma;
        l_b = l_b * cb + sumb;

        // ---- O += P V  (P from fragments, split hi/lo in-register) ----
        #pragma unroll
        for (int ks = 0; ks < 8; ks++) {
            uint32_t pah[4], pal[4];
            split2(accS[2 * ks][0],     accS[2 * ks][1],     pah[0], pal[0]);
            split2(accS[2 * ks][2],     accS[2 * ks][3],     pah[1], pal[1]);
            split2(accS[2 * ks + 1][0], accS[2 * ks + 1][1], pah[2], pal[2]);
            split2(accS[2 * ks + 1][2], accS[2 * ks + 1][3], pah[3], pal[3]);
            int colb = (ks * 16 + (lane >> 4) * 8) * 2;
            #pragma unroll
            for (int bj = 0; bj < 4; bj++) {
                uint32_t vhf[4], vlf[4];
                uint32_t vaddr = vb + (bj * 16 + rq) * FA_VS + colb;
                LDSM4(vhf, vaddr);
                LDSM4(vlf, vaddr + FA_VPL);
                #pragma unroll
                for (int hf = 0; hf < 2; hf++) {
                    int nf = bj * 2 + hf;
                    MMA_BF16(accO[nf], pah, vhf[hf], vhf[hf + 2]);
                    MMA_BF16(accO[nf], pah, vlf[hf], vlf[hf + 2]);
                    MMA_BF16(accO[nf], pal, vhf[hf], vhf[hf + 2]);
                }
            }
        }
    }

    // ---- normalize + write split planes ----
    float inva = 1.f / l_a, invb = 1.f / l_b;
    long long rowa = (long long)(b * T_ + m0 + wr0 + ra) * E_ + h * DH_;
    long long rowb = rowa + 8LL * E_;
    int c0 = (lane & 3) * 2;
    #pragma unroll
    for (int nf = 0; nf < 8; nf++) {
        int col = c0 + nf * 8;
        uint32_t hp, lp;
        split2(accO[nf][0] * inva, accO[nf][1] * inva, hp, lp);
        *(uint32_t*)(oh + rowa + col) = hp;
        *(uint32_t*)(ol + rowa + col) = lp;
        split2(accO[nf][2] * invb, accO[nf][3] * invb, hp, lp);
        *(uint32_t*)(oh + rowb + col) = hp;
        *(uint32_t*)(ol + rowb + col) = lp;
    }
}

// ========================= host =========================
static inline void split_launch(const float* src, bf16* hi, bf16* lo, long long n)
{
    int n4 = (int)(n / 4);
    split_kernel<<<(n4 + 255) / 256, 256>>>((const float4*)src, (__nv_bfloat162*)hi, (__nv_bfloat162*)lo, n4);
}

extern "C" void kernel_launch(void* const* d_in, const int* in_sizes, int n_in,
                              void* d_out, int out_size)
{
    const int*   idx  = (const int*)  d_in[0];
    const float* tok  = (const float*)d_in[1];
    const float* pos  = (const float*)d_in[2];
    const float* Wq   = (const float*)d_in[3];
    const float* Wk   = (const float*)d_in[4];
    const float* Wv   = (const float*)d_in[5];
    const float* Wo   = (const float*)d_in[6];
    const float* bo   = (const float*)d_in[7];
    const float* ln1g = (const float*)d_in[8];
    const float* ln1b = (const float*)d_in[9];
    const float* W1   = (const float*)d_in[10];
    const float* b1   = (const float*)d_in[11];
    const float* W2   = (const float*)d_in[12];
    const float* b2   = (const float*)d_in[13];
    const float* ln2g = (const float*)d_in[14];
    const float* ln2b = (const float*)d_in[15];
    const float* lnfg = (const float*)d_in[16];
    const float* lnfb = (const float*)d_in[17];
    const float* Wlm  = (const float*)d_in[18];
    const float* blm  = (const float*)d_in[19];
    float* out = (float*)d_out;

    bf16 *wqkvh,*wqkvl,*woh,*wol,*w1h,*w1l,*w2h,*w2l,*wlmh,*wlml;
    bf16 *hh,*hl,*qh,*ql,*kh,*kl,*vh,*vl,*vth,*vtl,*ohp,*olp,*ffh,*ffl;
    float *x;
    cudaGetSymbolAddress((void**)&wqkvh, g_wqkv_h); cudaGetSymbolAddress((void**)&wqkvl, g_wqkv_l);
    cudaGetSymbolAddress((void**)&woh, g_wo_h);  cudaGetSymbolAddress((void**)&wol, g_wo_l);
    cudaGetSymbolAddress((void**)&w1h, g_w1_h);  cudaGetSymbolAddress((void**)&w1l, g_w1_l);
    cudaGetSymbolAddress((void**)&w2h, g_w2_h);  cudaGetSymbolAddress((void**)&w2l, g_w2_l);
    cudaGetSymbolAddress((void**)&wlmh, g_wlm_h); cudaGetSymbolAddress((void**)&wlml, g_wlm_l);
    cudaGetSymbolAddress((void**)&hh, g_h_h);    cudaGetSymbolAddress((void**)&hl, g_h_l);
    cudaGetSymbolAddress((void**)&qh, g_q_h);    cudaGetSymbolAddress((void**)&ql, g_q_l);
    cudaGetSymbolAddress((void**)&kh, g_k_h);    cudaGetSymbolAddress((void**)&kl, g_k_l);
    cudaGetSymbolAddress((void**)&vh, g_v_h);    cudaGetSymbolAddress((void**)&vl, g_v_l);
    cudaGetSymbolAddress((void**)&vth, g_vt_h);  cudaGetSymbolAddress((void**)&vtl, g_vt_l);
    cudaGetSymbolAddress((void**)&ohp, g_o_h);   cudaGetSymbolAddress((void**)&olp, g_o_l);
    cudaGetSymbolAddress((void**)&ffh, g_ff_h);  cudaGetSymbolAddress((void**)&ffl, g_ff_l);
    cudaGetSymbolAddress((void**)&x, g_x);

    const int SM128 = 4 * (256 + 256) * 80;  // 163840
    cudaFuncSetAttribute(gemm_mma<128>, cudaFuncAttributeMaxDynamicSharedMemorySize, SM128);
    cudaFuncSetAttribute(flash_kernel,  cudaFuncAttributeMaxDynamicSharedMemorySize, FA_SMEM);

    const long long EE = (long long)E_ * E_;
    // split weights: QKV concatenated per layer [3E, E]
    for (int l = 0; l < L_; l++) {
        split_launch(Wq + l * EE, wqkvh + l * 3 * EE,          wqkvl + l * 3 * EE,          EE);
        split_launch(Wk + l * EE, wqkvh + l * 3 * EE + EE,     wqkvl + l * 3 * EE + EE,     EE);
        split_launch(Wv + l * EE, wqkvh + l * 3 * EE + 2 * EE, wqkvl + l * 3 * EE + 2 * EE, EE);
    }
    split_launch(Wo, woh, wol, (long long)L_*E_*E_);
    split_launch(W1, w1h, w1l, (long long)L_*DF_*E_);
    split_launch(W2, w2h, w2l, (long long)L_*E_*DF_);
    split_launch(Wlm, wlmh, wlml, (long long)V_*E_);

    const float scale = 1.0f / sqrtf((float)E_);

    embed_kernel<<<(int)(((long long)M_*E_ + 255)/256), 256>>>(idx, tok, pos, x);

    for (int l = 0; l < L_; l++) {
        layernorm_kernel<<<M_, 256>>>(x, ln1g + l*E_, ln1b + l*E_, hh, hl);

        // fused QKV: [2048, 2304] = h @ Wqkv^T, routed to q/k/v planes
        {
            dim3 g(3 * E_ / 128, M_ / 128, 1);
            gemm_mma<128><<<g, 256, SM128>>>(hh, hl, E_, 0, 0,
                wqkvh + l * 3 * EE, wqkvl + l * 3 * EE, E_, 0, 0,
                nullptr, qh, ql, kh, kl, vh, vl, E_,
                E_, 0, 0, nullptr, nullptr, 0, E_, 1);
        }

        {
            dim3 g(T_/64, B_*H_);
            transpose_vT<<<g, 256>>>(vh, vl, vth, vtl);
        }

        // fused attention
        {
            dim3 g(1, T_/128, B_*H_);
            flash_kernel<<<g, 256, FA_SMEM>>>(qh, ql, kh, kl, vth, vtl, ohp, olp, scale);
        }

        // x = x + O @ Wo^T + bo
        {
            dim3 g(E_/128, M_/128, 1);
            gemm_mma<128><<<g, 256, SM128>>>(ohp, olp, E_, 0, 0, woh + l*EE, wol + l*EE, E_, 0, 0,
                x, nullptr, nullptr, nullptr, nullptr, nullptr, nullptr, 0,
                E_, 0, 0, bo + l*E_, x, 0, E_, 1);
        }

        layernorm_kernel<<<M_, 256>>>(x, ln2g + l*E_, ln2b + l*E_, hh, hl);

        {
            dim3 g(DF_/128, M_/128, 1);
            gemm_mma<128><<<g, 256, SM128>>>(hh, hl, E_, 0, 0,
                w1h + (long long)l*DF_*E_, w1l + (long long)l*DF_*E_, E_, 0, 0,
                nullptr, ffh, ffl, nullptr, nullptr, nullptr, nullptr, 0,
                DF_, 0, 0, b1 + l*DF_, nullptr, 1, E_, 1);
        }
        {
            dim3 g(E_/128, M_/128, 1);
            gemm_mma<128><<<g, 256, SM128>>>(ffh, ffl, DF_, 0, 0,
                w2h + (long long)l*E_*DF_, w2l + (long long)l*E_*DF_, DF_, 0, 0,
                x, nullptr, nullptr, nullptr, nullptr, nullptr, nullptr, 0,
                E_, 0, 0, b2 + l*E_, x, 0, DF_, 1);
        }
    }

    layernorm_kernel<<<M_, 256>>>(x, lnfg, lnfb, hh, hl);
    {
        dim3 g(V_/128, M_/128, 1);
        gemm_mma<128><<<g, 256, SM128>>>(hh, hl, E_, 0, 0, wlmh, wlml, E_, 0, 0,
            out, nullptr, nullptr, nullptr, nullptr, nullptr, nullptr, 0,
            V_, 0, 0, blm, nullptr, 0, E_, 1);
    }
}